// round 13
// baseline (speedup 1.0000x reference)
#include <cuda_runtime.h>
#include <cuda_bf16.h>
#include <cstdint>
#include <cstddef>

// Problem constants
#define BATCH 4
#define HH 56
#define WW 56
#define CIN 256
#define CR 64          // reduced channels
#define GG 16          // groups
#define CGC 16         // channels per group
#define KS 7
#define KK 49
#define NSPAN 784      // K*K*G
#define MPIX 12544     // B*H*W

// Scratch (allocation-free: __device__ globals)
__device__ __align__(256) __nv_bfloat16 g_Rhi[(size_t)MPIX * CR];
__device__ __align__(256) __nv_bfloat16 g_Rlo[(size_t)MPIX * CR];

// ---------------------------------------------------------------------------
// Helpers
// ---------------------------------------------------------------------------
__device__ __forceinline__ uint32_t smem_u32(const void* p) {
    uint32_t a;
    asm("{ .reg .u64 t; cvta.to.shared.u64 t, %1; cvt.u32.u64 %0, t; }"
        : "=r"(a) : "l"(p));
    return a;
}
__device__ __forceinline__ void ldsm_x4(uint32_t r[4], uint32_t addr) {
    asm volatile("ldmatrix.sync.aligned.m8n8.x4.shared.b16 {%0,%1,%2,%3}, [%4];"
                 : "=r"(r[0]), "=r"(r[1]), "=r"(r[2]), "=r"(r[3]) : "r"(addr));
}
__device__ __forceinline__ void ldsm_x4t(uint32_t r[4], uint32_t addr) {
    asm volatile("ldmatrix.sync.aligned.m8n8.x4.trans.shared.b16 {%0,%1,%2,%3}, [%4];"
                 : "=r"(r[0]), "=r"(r[1]), "=r"(r[2]), "=r"(r[3]) : "r"(addr));
}
__device__ __forceinline__ void ldsm_x2t(uint32_t r[2], uint32_t addr) {
    asm volatile("ldmatrix.sync.aligned.m8n8.x2.trans.shared.b16 {%0,%1}, [%2];"
                 : "=r"(r[0]), "=r"(r[1]) : "r"(addr));
}
__device__ __forceinline__ void mma_bf16(float c[4], const uint32_t a[4],
                                         const uint32_t b[2]) {
    asm volatile(
        "mma.sync.aligned.m16n8k16.row.col.f32.bf16.bf16.f32 "
        "{%0,%1,%2,%3}, {%4,%5,%6,%7}, {%8,%9}, {%0,%1,%2,%3};"
        : "+f"(c[0]), "+f"(c[1]), "+f"(c[2]), "+f"(c[3])
        : "r"(a[0]), "r"(a[1]), "r"(a[2]), "r"(a[3]), "r"(b[0]), "r"(b[1]));
}
__device__ __forceinline__ void split2(float a, float b, uint32_t& hi, uint32_t& lo) {
    __nv_bfloat162 h = __floats2bfloat162_rn(a, b);
    float ra = a - __bfloat162float(h.x);
    float rb = b - __bfloat162float(h.y);
    __nv_bfloat162 l = __floats2bfloat162_rn(ra, rb);
    hi = *reinterpret_cast<uint32_t*>(&h);
    lo = *reinterpret_cast<uint32_t*>(&l);
}

#define RSTRIDE 144      // smem row stride in bytes (72 bf16)

// ---------------------------------------------------------------------------
// Kernel 1: R = relu(BN(x @ w_reduce)) -> split bf16 (g_Rhi, g_Rlo)
// BM=64, N=64, K=256 in 4 panels. 256 threads (8 warps: 4m x 2n). Grid 196.
// Both X and W split fp32 -> bf16 hi/lo inline during smem staging.
// ---------------------------------------------------------------------------
#define RA_HI 0
#define RA_LO 9216
#define RB_HI 18432
#define RB_LO 27648
#define RED_SMEM 36864

__global__ void __launch_bounds__(256) k_reduce_mma(
    const float* __restrict__ X, const float* __restrict__ W,
    const float* __restrict__ gamma, const float* __restrict__ beta,
    const float* __restrict__ mean, const float* __restrict__ var)
{
    extern __shared__ char smem[];
    __shared__ float s_s[64], s_sh[64];
    const uint32_t sb = smem_u32(smem);
    const int tid = threadIdx.x, w = tid >> 5, l = tid & 31;
    const int wm = w >> 1, wn = w & 1;
    const int rbase = wm * 16, cbase = wn * 32;
    const int bm = blockIdx.x * 64;

    if (tid < 64) {
        float s = gamma[tid] * rsqrtf(var[tid] + 1e-3f);
        s_s[tid] = s;
        s_sh[tid] = beta[tid] - mean[tid] * s;
    }

    float acc[4][4];
#pragma unroll
    for (int j = 0; j < 4; j++)
#pragma unroll
        for (int k = 0; k < 4; k++) acc[j][k] = 0.f;

    for (int p = 0; p < 4; p++) {
        const int k0 = p * 64;
        // A: X fp32 tile (64 rows x 64 k) -> split to RA_HI/RA_LO
#pragma unroll
        for (int it = 0; it < 4; it++) {
            int idx = tid + it * 256;          // 0..1023 float4s
            int row = idx >> 4, kq = idx & 15;
            float4 v = *(const float4*)(X + (size_t)(bm + row) * CIN + k0 + kq * 4);
            uint32_t h01, l01, h23, l23;
            split2(v.x, v.y, h01, l01);
            split2(v.z, v.w, h23, l23);
            char* d = smem + row * RSTRIDE + kq * 8;
            *(uint2*)(d + RA_HI) = make_uint2(h01, h23);
            *(uint2*)(d + RA_LO) = make_uint2(l01, l23);
        }
        // B: W fp32 panel (64 k x 64 n) -> split to RB_HI/RB_LO
#pragma unroll
        for (int it = 0; it < 4; it++) {
            int idx = tid + it * 256;          // 0..1023 float4s
            int row = idx >> 4, nq = idx & 15;
            float4 v = *(const float4*)(W + (size_t)(k0 + row) * CR + nq * 4);
            uint32_t h01, l01, h23, l23;
            split2(v.x, v.y, h01, l01);
            split2(v.z, v.w, h23, l23);
            char* d = smem + row * RSTRIDE + nq * 8;
            *(uint2*)(d + RB_HI) = make_uint2(h01, h23);
            *(uint2*)(d + RB_LO) = make_uint2(l01, l23);
        }
        __syncthreads();

#pragma unroll
        for (int ks = 0; ks < 4; ks++) {
            uint32_t ah[4], al[4];
            uint32_t ad = sb + (rbase + (l & 15)) * RSTRIDE + (ks * 16 + (l >> 4) * 8) * 2;
            ldsm_x4(ah, ad + RA_HI);
            ldsm_x4(al, ad + RA_LO);
            uint32_t bh[4][2], bl[4][2];
#pragma unroll
            for (int np = 0; np < 4; np += 2) {
                uint32_t bd = sb
                    + (ks * 16 + (l & 7) + ((l >> 3) & 1) * 8) * RSTRIDE
                    + (cbase + (np + (l >> 4)) * 8) * 2;
                uint32_t r[4];
                ldsm_x4t(r, bd + RB_HI);
                bh[np][0] = r[0]; bh[np][1] = r[1];
                bh[np + 1][0] = r[2]; bh[np + 1][1] = r[3];
                ldsm_x4t(r, bd + RB_LO);
                bl[np][0] = r[0]; bl[np][1] = r[1];
                bl[np + 1][0] = r[2]; bl[np + 1][1] = r[3];
            }
#pragma unroll
            for (int nt = 0; nt < 4; nt++) {
                mma_bf16(acc[nt], ah, bh[nt]);
                mma_bf16(acc[nt], ah, bl[nt]);
                mma_bf16(acc[nt], al, bh[nt]);
            }
        }
        __syncthreads();
    }

    const int gid = l >> 2, tig = l & 3;
#pragma unroll
    for (int nt = 0; nt < 4; nt++) {
        int col = cbase + nt * 8 + tig * 2;
        float s0 = s_s[col], s1 = s_s[col + 1];
        float h0 = s_sh[col], h1 = s_sh[col + 1];
#pragma unroll
        for (int half = 0; half < 2; half++) {
            int row = bm + rbase + gid + half * 8;
            float v0 = fmaxf(acc[nt][half * 2] * s0 + h0, 0.f);
            float v1 = fmaxf(acc[nt][half * 2 + 1] * s1 + h1, 0.f);
            uint32_t hi, lo;
            split2(v0, v1, hi, lo);
            *(uint32_t*)(g_Rhi + (size_t)row * CR + col) = hi;
            *(uint32_t*)(g_Rlo + (size_t)row * CR + col) = lo;
        }
    }
}

// ---------------------------------------------------------------------------
// Kernel 2 (FUSED span+involution): one block = 8x8 px tile x 1 group.
// Phase 1: kgen_tile = R_tile @ Wspan_slice + bias (MMA) -> smem kg[tap][px].
//   Wspan slice staged fp32 -> split bf16 inline (L2-hot: reused by 196 blks).
//   x-halo LDGs issued BEFORE phase 1 (values parked in regs; latency hidden
//   behind the MMA), stored to the overlaid xs region after the epilogue sync.
// Phase 2: R11 gather mainloop.
// ---------------------------------------------------------------------------
#define F_BHI 0
#define F_BLO 9216
#define F_AHI 18432
#define F_ALO 27648
#define F_KGB 36864                    // kg byte offset
#define F_SMEM (F_KGB + KK * 64 * 4)   // 49408
#define XSTR 24                        // xs floats per (r,c) slot (16 + 8 pad)

__global__ void __launch_bounds__(128, 4) k_spaninv(
    const float* __restrict__ X, const float* __restrict__ Ws,
    const float* __restrict__ bsp, float* __restrict__ O)
{
    extern __shared__ char smem[];
    float* sm = (float*)smem;
    float* xs = sm;                      // overlays B/A region (phase 2)
    float* kg = sm + F_KGB / 4;          // [49][64]
    const uint32_t sb = smem_u32(smem);
    const int tid = threadIdx.x, w = tid >> 5, l = tid & 31;
    const int rbase = w * 16;

    const int bw = blockIdx.x * 8;
    const int bh = blockIdx.y * 8;
    const int bz = blockIdx.z;           // b*16 + g
    const int b = bz >> 4;
    const int g = bz & 15;

    // ---- x-halo prefetch into registers (stores deferred to phase 2)
    float4 hx[7];
#pragma unroll
    for (int it = 0; it < 7; it++) {
        int i = tid + it * 128;          // 0..895 (784 valid)
        int pos = i >> 2, q = i & 3;
        int r = pos / 14, c = pos - r * 14;
        int y = bh + r - 3, x = bw + c - 3;
        hx[it] = make_float4(0.f, 0.f, 0.f, 0.f);
        if (i < 784 && (unsigned)y < (unsigned)HH && (unsigned)x < (unsigned)WW)
            hx[it] = *(const float4*)(X + ((size_t)(b * HH + y) * WW + x) * CIN
                                        + g * CGC + q * 4);
    }

    // ---- Phase 1 staging: A = R tile (pre-split), B = w_span slice (inline split)
#pragma unroll
    for (int it = 0; it < 8; it++) {
        int idx = tid + it * 128;        // 0..1023
        int sel = idx >> 9, j = idx & 511;
        int row = j >> 3, kq = j & 7;    // row: pixel idx in tile
        size_t pix = (size_t)(b * HH + bh + (row >> 3)) * WW + (bw + (row & 7));
        const __nv_bfloat16* src = sel ? (g_Rlo + pix * CR) : (g_Rhi + pix * CR);
        int soff = sel ? F_ALO : F_AHI;
        *(uint4*)(smem + soff + row * RSTRIDE + kq * 16) = ((const uint4*)src)[kq];
    }
#pragma unroll
    for (int it = 0; it < 7; it++) {
        int idx = tid + it * 128;        // 0..895: row 0..63 x c4 0..13
        int row = idx / 14, c4 = idx - row * 14;
        const float* wsrc = Ws + (size_t)row * NSPAN + g * KK;
        float f0 = 0.f, f1 = 0.f, f2 = 0.f, f3 = 0.f;
        int col = c4 * 4;
        if (col < KK)     f0 = wsrc[col];
        if (col + 1 < KK) f1 = wsrc[col + 1];
        if (col + 2 < KK) f2 = wsrc[col + 2];
        if (col + 3 < KK) f3 = wsrc[col + 3];
        uint32_t h01, l01, h23, l23;
        split2(f0, f1, h01, l01);
        split2(f2, f3, h23, l23);
        char* d = smem + row * RSTRIDE + c4 * 8;
        *(uint2*)(d + F_BHI) = make_uint2(h01, h23);
        *(uint2*)(d + F_BLO) = make_uint2(l01, l23);
    }
    __syncthreads();

    // ---- Phase 1 MMA: M=64 (4 warps x 16), N=56 (49 valid), K=64
    float acc[7][4];
#pragma unroll
    for (int j = 0; j < 7; j++)
#pragma unroll
        for (int k = 0; k < 4; k++) acc[j][k] = 0.f;

#pragma unroll
    for (int ks = 0; ks < 4; ks++) {
        uint32_t ah[4], al[4];
        {
            uint32_t ad = sb + (rbase + (l & 15)) * RSTRIDE + (ks * 16 + (l >> 4) * 8) * 2;
            ldsm_x4(ah, ad + F_AHI);
            ldsm_x4(al, ad + F_ALO);
        }
        uint32_t bh[7][2], bl[7][2];
#pragma unroll
        for (int np = 0; np < 6; np += 2) {
            uint32_t bd = sb
                + (ks * 16 + (l & 7) + ((l >> 3) & 1) * 8) * RSTRIDE
                + ((np + (l >> 4)) * 8) * 2;
            uint32_t r[4];
            ldsm_x4t(r, bd + F_BHI);
            bh[np][0] = r[0]; bh[np][1] = r[1];
            bh[np + 1][0] = r[2]; bh[np + 1][1] = r[3];
            ldsm_x4t(r, bd + F_BLO);
            bl[np][0] = r[0]; bl[np][1] = r[1];
            bl[np + 1][0] = r[2]; bl[np + 1][1] = r[3];
        }
        {
            uint32_t bd = sb
                + (ks * 16 + (l & 7) + ((l >> 3) & 1) * 8) * RSTRIDE
                + (6 * 8) * 2;
            ldsm_x2t(bh[6], bd + F_BHI);
            ldsm_x2t(bl[6], bd + F_BLO);
        }
#pragma unroll
        for (int nt = 0; nt < 7; nt++) {
            mma_bf16(acc[nt], ah, bh[nt]);
            mma_bf16(acc[nt], ah, bl[nt]);
            mma_bf16(acc[nt], al, bh[nt]);
        }
    }

    // ---- epilogue: + bias -> kg[tap][px] in smem (taps >= 49 dropped)
    {
        const int gid = l >> 2, tig = l & 3;
        const float* bg = bsp + g * KK;
#pragma unroll
        for (int nt = 0; nt < 7; nt++) {
            int col = nt * 8 + tig * 2;
            float b0 = (col < KK) ? bg[col] : 0.f;
            float b1 = (col + 1 < KK) ? bg[col + 1] : 0.f;
#pragma unroll
            for (int half = 0; half < 2; half++) {
                int row = rbase + gid + half * 8;
                if (col < KK)     kg[col * 64 + row]       = acc[nt][half * 2] + b0;
                if (col + 1 < KK) kg[(col + 1) * 64 + row] = acc[nt][half * 2 + 1] + b1;
            }
        }
    }
    __syncthreads();   // all ldsm reads of A/B done; kg complete

    // ---- Phase 2 staging: flush prefetched x halo to the overlaid region
#pragma unroll
    for (int it = 0; it < 7; it++) {
        int i = tid + it * 128;
        if (i < 784) {
            int pos = i >> 2, q = i & 3;
            *(float4*)&xs[pos * XSTR + q * 4] = hx[it];
        }
    }
    __syncthreads();

    // ---- Phase 2 mainloop
    const int q2 = tid & 7;                 // channel pair (2 ch)
    const int pb = tid >> 3;                // 2x2 pixel block (0..15)
    const int px0 = (pb & 3) * 2, py0 = (pb >> 2) * 2;
    const int chb = q2 * 2;
    const float* kgA = kg + py0 * 8 + px0;   // pixels p0, p0+1
    const float* kgB = kgA + 8;              // pixels p0+8, p0+9

    float2 a00 = make_float2(0.f, 0.f);
    float2 a01 = a00, a10 = a00, a11 = a00;

#pragma unroll
    for (int r8 = 0; r8 < 8; r8++) {
        float2 xr[8];
        const float* xrow = &xs[((py0 + r8) * 14 + px0) * XSTR + chb];
#pragma unroll
        for (int j = 0; j < 8; j++)
            xr[j] = *(const float2*)&xrow[j * XSTR];
        if (r8 <= 6) {                 // row pyo=0: kh = r8
#pragma unroll
            for (int kw = 0; kw < 7; kw++) {
                float2 wp = *(const float2*)&kgA[(r8 * 7 + kw) * 64];
                a00.x += wp.x * xr[kw].x;     a01.x += wp.y * xr[kw + 1].x;
                a00.y += wp.x * xr[kw].y;     a01.y += wp.y * xr[kw + 1].y;
            }
        }
        if (r8 >= 1) {                 // row pyo=1: kh = r8-1
#pragma unroll
            for (int kw = 0; kw < 7; kw++) {
                float2 wp = *(const float2*)&kgB[((r8 - 1) * 7 + kw) * 64];
                a10.x += wp.x * xr[kw].x;     a11.x += wp.y * xr[kw + 1].x;
                a10.y += wp.x * xr[kw].y;     a11.y += wp.y * xr[kw + 1].y;
            }
        }
    }

    const size_t pix00 = (size_t)(b * HH + bh + py0) * WW + (bw + px0);
    float* obase = O + pix00 * CIN + g * CGC + chb;
    *(float2*)obase = a00;
    *(float2*)(obase + CIN) = a01;
    *(float2*)(obase + (size_t)WW * CIN) = a10;
    *(float2*)(obase + (size_t)WW * CIN + CIN) = a11;
}

// ---------------------------------------------------------------------------
extern "C" void kernel_launch(void* const* d_in, const int* in_sizes, int n_in,
                              void* d_out, int out_size)
{
    const float* x        = (const float*)d_in[0];
    const float* w_reduce = (const float*)d_in[1];
    const float* gamma    = (const float*)d_in[2];
    const float* beta     = (const float*)d_in[3];
    const float* mean     = (const float*)d_in[4];
    const float* var      = (const float*)d_in[5];
    const float* w_span   = (const float*)d_in[6];
    const float* b_span   = (const float*)d_in[7];
    float* out = (float*)d_out;

    cudaFuncSetAttribute(k_reduce_mma, cudaFuncAttributeMaxDynamicSharedMemorySize, RED_SMEM);
    cudaFuncSetAttribute(k_spaninv,    cudaFuncAttributeMaxDynamicSharedMemorySize, F_SMEM);

    k_reduce_mma<<<MPIX / 64, 256, RED_SMEM>>>(x, w_reduce, gamma, beta, mean, var);
    k_spaninv<<<dim3(WW / 8, HH / 8, BATCH * GG), 128, F_SMEM>>>(x, w_span, b_span, out);
}

// round 16
// speedup vs baseline: 1.0524x; 1.0524x over previous
#include <cuda_runtime.h>
#include <cuda_bf16.h>
#include <cstdint>
#include <cstddef>

// Problem constants
#define BATCH 4
#define HH 56
#define WW 56
#define CIN 256
#define CR 64          // reduced channels
#define GG 16          // groups
#define CGC 16         // channels per group
#define KS 7
#define KK 49
#define NSPAN 784      // K*K*G
#define MPIX 12544     // B*H*W

// Scratch (allocation-free: __device__ globals)
__device__ __align__(256) __nv_bfloat16 g_Rhi[(size_t)MPIX * CR];
__device__ __align__(256) __nv_bfloat16 g_Rlo[(size_t)MPIX * CR];
// w_span re-laid out group-major & padded: [g][k][64] (cols 49..63 zero)
__device__ __align__(256) __nv_bfloat16 g_Wsghi[GG * CR * 64];
__device__ __align__(256) __nv_bfloat16 g_Wsglo[GG * CR * 64];

// ---------------------------------------------------------------------------
// Helpers
// ---------------------------------------------------------------------------
__device__ __forceinline__ uint32_t smem_u32(const void* p) {
    uint32_t a;
    asm("{ .reg .u64 t; cvta.to.shared.u64 t, %1; cvt.u32.u64 %0, t; }"
        : "=r"(a) : "l"(p));
    return a;
}
__device__ __forceinline__ void ldsm_x4(uint32_t r[4], uint32_t addr) {
    asm volatile("ldmatrix.sync.aligned.m8n8.x4.shared.b16 {%0,%1,%2,%3}, [%4];"
                 : "=r"(r[0]), "=r"(r[1]), "=r"(r[2]), "=r"(r[3]) : "r"(addr));
}
__device__ __forceinline__ void ldsm_x4t(uint32_t r[4], uint32_t addr) {
    asm volatile("ldmatrix.sync.aligned.m8n8.x4.trans.shared.b16 {%0,%1,%2,%3}, [%4];"
                 : "=r"(r[0]), "=r"(r[1]), "=r"(r[2]), "=r"(r[3]) : "r"(addr));
}
__device__ __forceinline__ void ldsm_x2t(uint32_t r[2], uint32_t addr) {
    asm volatile("ldmatrix.sync.aligned.m8n8.x2.trans.shared.b16 {%0,%1}, [%2];"
                 : "=r"(r[0]), "=r"(r[1]) : "r"(addr));
}
__device__ __forceinline__ void mma_bf16(float c[4], const uint32_t a[4],
                                         const uint32_t b[2]) {
    asm volatile(
        "mma.sync.aligned.m16n8k16.row.col.f32.bf16.bf16.f32 "
        "{%0,%1,%2,%3}, {%4,%5,%6,%7}, {%8,%9}, {%0,%1,%2,%3};"
        : "+f"(c[0]), "+f"(c[1]), "+f"(c[2]), "+f"(c[3])
        : "r"(a[0]), "r"(a[1]), "r"(a[2]), "r"(a[3]), "r"(b[0]), "r"(b[1]));
}
__device__ __forceinline__ void split2(float a, float b, uint32_t& hi, uint32_t& lo) {
    __nv_bfloat162 h = __floats2bfloat162_rn(a, b);
    float ra = a - __bfloat162float(h.x);
    float rb = b - __bfloat162float(h.y);
    __nv_bfloat162 l = __floats2bfloat162_rn(ra, rb);
    hi = *reinterpret_cast<uint32_t*>(&h);
    lo = *reinterpret_cast<uint32_t*>(&l);
}
__device__ __forceinline__ void split1(float a, __nv_bfloat16& hi, __nv_bfloat16& lo) {
    hi = __float2bfloat16(a);
    lo = __float2bfloat16(a - __bfloat162float(hi));
}

#define RSTRIDE 144      // smem row stride in bytes (72 bf16)
#define NSG (GG * CR * 64)   // 65536 w_span repack items

// ---------------------------------------------------------------------------
// Kernel 1: R = relu(BN(x @ w_reduce)) -> split bf16 (g_Rhi, g_Rlo)
// BM=64, N=64, K=256 in 4 panels. 256 threads (8 warps: 4m x 2n). Grid 196.
// X and W split inline. TAIL: w_span group-major repack -> g_Wsghi/g_Wsglo
// (spread over all 196 blocks; separate output buffer, no sync needed).
// ---------------------------------------------------------------------------
#define RA_HI 0
#define RA_LO 9216
#define RB_HI 18432
#define RB_LO 27648
#define RED_SMEM 36864

__global__ void __launch_bounds__(256) k_reduce_mma(
    const float* __restrict__ X, const float* __restrict__ W,
    const float* __restrict__ Ws,
    const float* __restrict__ gamma, const float* __restrict__ beta,
    const float* __restrict__ mean, const float* __restrict__ var)
{
    extern __shared__ char smem[];
    __shared__ float s_s[64], s_sh[64];
    const uint32_t sb = smem_u32(smem);
    const int tid = threadIdx.x, w = tid >> 5, l = tid & 31;
    const int wm = w >> 1, wn = w & 1;
    const int rbase = wm * 16, cbase = wn * 32;
    const int bm = blockIdx.x * 64;

    if (tid < 64) {
        float s = gamma[tid] * rsqrtf(var[tid] + 1e-3f);
        s_s[tid] = s;
        s_sh[tid] = beta[tid] - mean[tid] * s;
    }

    float acc[4][4];
#pragma unroll
    for (int j = 0; j < 4; j++)
#pragma unroll
        for (int k = 0; k < 4; k++) acc[j][k] = 0.f;

    for (int p = 0; p < 4; p++) {
        const int k0 = p * 64;
        // A: X fp32 tile (64 rows x 64 k) -> split to RA_HI/RA_LO
#pragma unroll
        for (int it = 0; it < 4; it++) {
            int idx = tid + it * 256;          // 0..1023 float4s
            int row = idx >> 4, kq = idx & 15;
            float4 v = *(const float4*)(X + (size_t)(bm + row) * CIN + k0 + kq * 4);
            uint32_t h01, l01, h23, l23;
            split2(v.x, v.y, h01, l01);
            split2(v.z, v.w, h23, l23);
            char* d = smem + row * RSTRIDE + kq * 8;
            *(uint2*)(d + RA_HI) = make_uint2(h01, h23);
            *(uint2*)(d + RA_LO) = make_uint2(l01, l23);
        }
        // B: W fp32 panel (64 k x 64 n) -> split to RB_HI/RB_LO
#pragma unroll
        for (int it = 0; it < 4; it++) {
            int idx = tid + it * 256;          // 0..1023 float4s
            int row = idx >> 4, nq = idx & 15;
            float4 v = *(const float4*)(W + (size_t)(k0 + row) * CR + nq * 4);
            uint32_t h01, l01, h23, l23;
            split2(v.x, v.y, h01, l01);
            split2(v.z, v.w, h23, l23);
            char* d = smem + row * RSTRIDE + nq * 8;
            *(uint2*)(d + RB_HI) = make_uint2(h01, h23);
            *(uint2*)(d + RB_LO) = make_uint2(l01, l23);
        }
        __syncthreads();

#pragma unroll
        for (int ks = 0; ks < 4; ks++) {
            uint32_t ah[4], al[4];
            uint32_t ad = sb + (rbase + (l & 15)) * RSTRIDE + (ks * 16 + (l >> 4) * 8) * 2;
            ldsm_x4(ah, ad + RA_HI);
            ldsm_x4(al, ad + RA_LO);
            uint32_t bh[4][2], bl[4][2];
#pragma unroll
            for (int np = 0; np < 4; np += 2) {
                uint32_t bd = sb
                    + (ks * 16 + (l & 7) + ((l >> 3) & 1) * 8) * RSTRIDE
                    + (cbase + (np + (l >> 4)) * 8) * 2;
                uint32_t r[4];
                ldsm_x4t(r, bd + RB_HI);
                bh[np][0] = r[0]; bh[np][1] = r[1];
                bh[np + 1][0] = r[2]; bh[np + 1][1] = r[3];
                ldsm_x4t(r, bd + RB_LO);
                bl[np][0] = r[0]; bl[np][1] = r[1];
                bl[np + 1][0] = r[2]; bl[np + 1][1] = r[3];
            }
#pragma unroll
            for (int nt = 0; nt < 4; nt++) {
                mma_bf16(acc[nt], ah, bh[nt]);
                mma_bf16(acc[nt], ah, bl[nt]);
                mma_bf16(acc[nt], al, bh[nt]);
            }
        }
        __syncthreads();
    }

    const int gid = l >> 2, tig = l & 3;
#pragma unroll
    for (int nt = 0; nt < 4; nt++) {
        int col = cbase + nt * 8 + tig * 2;
        float s0 = s_s[col], s1 = s_s[col + 1];
        float h0 = s_sh[col], h1 = s_sh[col + 1];
#pragma unroll
        for (int half = 0; half < 2; half++) {
            int row = bm + rbase + gid + half * 8;
            float v0 = fmaxf(acc[nt][half * 2] * s0 + h0, 0.f);
            float v1 = fmaxf(acc[nt][half * 2 + 1] * s1 + h1, 0.f);
            uint32_t hi, lo;
            split2(v0, v1, hi, lo);
            *(uint32_t*)(g_Rhi + (size_t)row * CR + col) = hi;
            *(uint32_t*)(g_Rlo + (size_t)row * CR + col) = lo;
        }
    }

    // TAIL: w_span group-major repack (0.5 MB one-time; <=2 items/thread)
    for (int i = blockIdx.x * 256 + tid; i < NSG; i += 196 * 256) {
        int g = i >> 12, k = (i >> 6) & 63, c = i & 63;
        float v = (c < KK) ? Ws[(size_t)k * NSPAN + g * KK + c] : 0.f;
        __nv_bfloat16 hi, lo;
        split1(v, hi, lo);
        g_Wsghi[i] = hi;
        g_Wsglo[i] = lo;
    }
}

// ---------------------------------------------------------------------------
// Kernel 2 (FUSED span+involution): one block = 8x8 px tile x 1 group.
// Phase 1: kgen_tile = R_tile @ Wspan_slice + bias (MMA) -> smem kg[tap][px].
// Phase 2: x-halo overlay onto dead A/B smem, then gather mainloop.
// (R12 version: vectorized pre-split B staging, no register prefetch.)
// ---------------------------------------------------------------------------
#define F_BHI 0
#define F_BLO 9216
#define F_AHI 18432
#define F_ALO 27648
#define F_KGB 36864                    // kg byte offset
#define F_SMEM (F_KGB + KK * 64 * 4)   // 49408
#define XSTR 24                        // xs floats per (r,c) slot (16 + 8 pad)

__global__ void __launch_bounds__(128, 4) k_spaninv(
    const float* __restrict__ X, const float* __restrict__ bsp,
    float* __restrict__ O)
{
    extern __shared__ char smem[];
    float* sm = (float*)smem;
    float* xs = sm;                      // overlays B/A region (phase 2)
    float* kg = sm + F_KGB / 4;          // [49][64]
    const uint32_t sb = smem_u32(smem);
    const int tid = threadIdx.x, w = tid >> 5, l = tid & 31;
    const int rbase = w * 16;

    const int bw = blockIdx.x * 8;
    const int bh = blockIdx.y * 8;
    const int bz = blockIdx.z;           // b*16 + g
    const int b = bz >> 4;
    const int g = bz & 15;

    // ---- Phase 1 staging: A = R tile (64 px rows), B = w_span group slice
#pragma unroll
    for (int it = 0; it < 8; it++) {
        int idx = tid + it * 128;        // 0..1023
        int sel = idx >> 9, j = idx & 511;
        int row = j >> 3, kq = j & 7;    // row: pixel idx in tile
        size_t pix = (size_t)(b * HH + bh + (row >> 3)) * WW + (bw + (row & 7));
        const __nv_bfloat16* src = sel ? (g_Rlo + pix * CR) : (g_Rhi + pix * CR);
        int soff = sel ? F_ALO : F_AHI;
        *(uint4*)(smem + soff + row * RSTRIDE + kq * 16) = ((const uint4*)src)[kq];
    }
#pragma unroll
    for (int it = 0; it < 7; it++) {
        int idx = tid + it * 128;        // 0..895
        int sel = (idx >= 448) ? 1 : 0;
        int j = sel ? idx - 448 : idx;
        int row = j / 7, nq = j - row * 7;
        const __nv_bfloat16* src = sel ? (g_Wsglo + ((size_t)g * CR + row) * 64)
                                       : (g_Wsghi + ((size_t)g * CR + row) * 64);
        int soff = sel ? F_BLO : F_BHI;
        *(uint4*)(smem + soff + row * RSTRIDE + nq * 16) = ((const uint4*)src)[nq];
    }
    __syncthreads();

    // ---- Phase 1 MMA: M=64 (4 warps x 16), N=56 (49 valid), K=64
    float acc[7][4];
#pragma unroll
    for (int j = 0; j < 7; j++)
#pragma unroll
        for (int k = 0; k < 4; k++) acc[j][k] = 0.f;

#pragma unroll
    for (int ks = 0; ks < 4; ks++) {
        uint32_t ah[4], al[4];
        {
            uint32_t ad = sb + (rbase + (l & 15)) * RSTRIDE + (ks * 16 + (l >> 4) * 8) * 2;
            ldsm_x4(ah, ad + F_AHI);
            ldsm_x4(al, ad + F_ALO);
        }
        uint32_t bh[7][2], bl[7][2];
#pragma unroll
        for (int np = 0; np < 6; np += 2) {
            uint32_t bd = sb
                + (ks * 16 + (l & 7) + ((l >> 3) & 1) * 8) * RSTRIDE
                + ((np + (l >> 4)) * 8) * 2;
            uint32_t r[4];
            ldsm_x4t(r, bd + F_BHI);
            bh[np][0] = r[0]; bh[np][1] = r[1];
            bh[np + 1][0] = r[2]; bh[np + 1][1] = r[3];
            ldsm_x4t(r, bd + F_BLO);
            bl[np][0] = r[0]; bl[np][1] = r[1];
            bl[np + 1][0] = r[2]; bl[np + 1][1] = r[3];
        }
        {
            uint32_t bd = sb
                + (ks * 16 + (l & 7) + ((l >> 3) & 1) * 8) * RSTRIDE
                + (6 * 8) * 2;
            ldsm_x2t(bh[6], bd + F_BHI);
            ldsm_x2t(bl[6], bd + F_BLO);
        }
#pragma unroll
        for (int nt = 0; nt < 7; nt++) {
            mma_bf16(acc[nt], ah, bh[nt]);
            mma_bf16(acc[nt], ah, bl[nt]);
            mma_bf16(acc[nt], al, bh[nt]);
        }
    }

    // ---- epilogue: + bias -> kg[tap][px] in smem (taps >= 49 dropped)
    {
        const int gid = l >> 2, tig = l & 3;
        const float* bg = bsp + g * KK;
#pragma unroll
        for (int nt = 0; nt < 7; nt++) {
            int col = nt * 8 + tig * 2;
            float b0 = (col < KK) ? bg[col] : 0.f;
            float b1 = (col + 1 < KK) ? bg[col + 1] : 0.f;
#pragma unroll
            for (int half = 0; half < 2; half++) {
                int row = rbase + gid + half * 8;
                if (col < KK)     kg[col * 64 + row]       = acc[nt][half * 2] + b0;
                if (col + 1 < KK) kg[(col + 1) * 64 + row] = acc[nt][half * 2 + 1] + b1;
            }
        }
    }
    __syncthreads();   // all ldsm reads of A/B done; kg complete

    // ---- Phase 2 staging: x halo overlays the dead A/B region
#pragma unroll
    for (int it = 0; it < 6; it++) {
        int i = tid + it * 128;
        int pos = i >> 2, q = i & 3;
        int r = pos / 14, c = pos - r * 14;
        int y = bh + r - 3, x = bw + c - 3;
        float4 v = make_float4(0.f, 0.f, 0.f, 0.f);
        if ((unsigned)y < (unsigned)HH && (unsigned)x < (unsigned)WW)
            v = *(const float4*)(X + ((size_t)(b * HH + y) * WW + x) * CIN
                                   + g * CGC + q * 4);
        *(float4*)&xs[pos * XSTR + q * 4] = v;
    }
    if (tid < 16) {
        int i = tid + 768;
        int pos = i >> 2, q = i & 3;
        int r = pos / 14, c = pos - r * 14;
        int y = bh + r - 3, x = bw + c - 3;
        float4 v = make_float4(0.f, 0.f, 0.f, 0.f);
        if ((unsigned)y < (unsigned)HH && (unsigned)x < (unsigned)WW)
            v = *(const float4*)(X + ((size_t)(b * HH + y) * WW + x) * CIN
                                   + g * CGC + q * 4);
        *(float4*)&xs[pos * XSTR + q * 4] = v;
    }
    __syncthreads();

    // ---- Phase 2 mainloop
    const int q2 = tid & 7;                 // channel pair (2 ch)
    const int pb = tid >> 3;                // 2x2 pixel block (0..15)
    const int px0 = (pb & 3) * 2, py0 = (pb >> 2) * 2;
    const int chb = q2 * 2;
    const float* kgA = kg + py0 * 8 + px0;   // pixels p0, p0+1
    const float* kgB = kgA + 8;              // pixels p0+8, p0+9

    float2 a00 = make_float2(0.f, 0.f);
    float2 a01 = a00, a10 = a00, a11 = a00;

#pragma unroll
    for (int r8 = 0; r8 < 8; r8++) {
        float2 xr[8];
        const float* xrow = &xs[((py0 + r8) * 14 + px0) * XSTR + chb];
#pragma unroll
        for (int j = 0; j < 8; j++)
            xr[j] = *(const float2*)&xrow[j * XSTR];
        if (r8 <= 6) {                 // row pyo=0: kh = r8
#pragma unroll
            for (int kw = 0; kw < 7; kw++) {
                float2 wp = *(const float2*)&kgA[(r8 * 7 + kw) * 64];
                a00.x += wp.x * xr[kw].x;     a01.x += wp.y * xr[kw + 1].x;
                a00.y += wp.x * xr[kw].y;     a01.y += wp.y * xr[kw + 1].y;
            }
        }
        if (r8 >= 1) {                 // row pyo=1: kh = r8-1
#pragma unroll
            for (int kw = 0; kw < 7; kw++) {
                float2 wp = *(const float2*)&kgB[((r8 - 1) * 7 + kw) * 64];
                a10.x += wp.x * xr[kw].x;     a11.x += wp.y * xr[kw + 1].x;
                a10.y += wp.x * xr[kw].y;     a11.y += wp.y * xr[kw + 1].y;
            }
        }
    }

    const size_t pix00 = (size_t)(b * HH + bh + py0) * WW + (bw + px0);
    float* obase = O + pix00 * CIN + g * CGC + chb;
    *(float2*)obase = a00;
    *(float2*)(obase + CIN) = a01;
    *(float2*)(obase + (size_t)WW * CIN) = a10;
    *(float2*)(obase + (size_t)WW * CIN + CIN) = a11;
}

// ---------------------------------------------------------------------------
extern "C" void kernel_launch(void* const* d_in, const int* in_sizes, int n_in,
                              void* d_out, int out_size)
{
    const float* x        = (const float*)d_in[0];
    const float* w_reduce = (const float*)d_in[1];
    const float* gamma    = (const float*)d_in[2];
    const float* beta     = (const float*)d_in[3];
    const float* mean     = (const float*)d_in[4];
    const float* var      = (const float*)d_in[5];
    const float* w_span   = (const float*)d_in[6];
    const float* b_span   = (const float*)d_in[7];
    float* out = (float*)d_out;

    cudaFuncSetAttribute(k_reduce_mma, cudaFuncAttributeMaxDynamicSharedMemorySize, RED_SMEM);
    cudaFuncSetAttribute(k_spaninv,    cudaFuncAttributeMaxDynamicSharedMemorySize, F_SMEM);

    k_reduce_mma<<<MPIX / 64, 256, RED_SMEM>>>(x, w_reduce, w_span,
                                               gamma, beta, mean, var);
    k_spaninv<<<dim3(WW / 8, HH / 8, BATCH * GG), 128, F_SMEM>>>(x, b_span, out);
}